// round 1
// baseline (speedup 1.0000x reference)
#include <cuda_runtime.h>
#include <cstdint>

#define BS 4
#define SEQ 1024
#define DIN 1024
#define DOUT 1024
#define NKR 32   // N_SKILLS * RANK
#define NROUTE 40 // 8 mw + 32 y

// ---------------- scratch (no allocations allowed) ----------------
__device__ float g_Y[BS * NKR * SEQ];     // y = x@A, transposed [b][kr][s]; becomes inclusive cumsum
__device__ float g_mw[BS * SEQ * 8];      // router logits
__device__ int   g_meta[8];               // [0..3]=thresh per batch, [4..7]=pad_start per batch

// ---------------- K1: mask params ----------------
__global__ void mask_kernel(const int* __restrict__ inst, const int* __restrict__ pad) {
    int b = blockIdx.x;
    const int* ib = inst + b * SEQ;
    const int* pb = pad + b * SEQ;
    __shared__ int s_sum, s_fi, s_fp;
    if (threadIdx.x == 0) { s_sum = 0; s_fi = 1 << 30; s_fp = 1 << 30; }
    __syncthreads();
    int lsum = 0, lfi = 1 << 30, lfp = 1 << 30;
    for (int i = threadIdx.x; i < SEQ; i += blockDim.x) {
        int iv = ib[i];
        lsum += iv;
        if (iv && i < lfi) lfi = i;
        if (pb[i] && i < lfp) lfp = i;
    }
    atomicAdd(&s_sum, lsum);
    atomicMin(&s_fi, lfi);
    atomicMin(&s_fp, lfp);
    __syncthreads();
    if (threadIdx.x == 0) {
        int fi = (s_fi == (1 << 30)) ? 0 : s_fi;   // jnp.argmax convention: all-zero -> 0
        int fp = (s_fp == (1 << 30)) ? 0 : s_fp;
        g_meta[b] = fi + s_sum;   // thresh = first_one + n_ones
        g_meta[4 + b] = fp;       // pad start
    }
}

// ---------------- K2: router GEMM  mw = x@phi, y = x@A_flat ----------------
// 128 blocks of 32 tokens; 256 threads; BK=32
__global__ void __launch_bounds__(256) router_kernel(const float* __restrict__ X,
                                                     const float* __restrict__ phi,
                                                     const float* __restrict__ A) {
    __shared__ float xs[32][33];
    __shared__ float ws[32][NROUTE];
    int t0 = blockIdx.x * 32;            // global token base
    int b = t0 >> 10;
    int s0 = t0 & 1023;
    int tid = threadIdx.x;
    int tt = tid & 31;                   // token within tile
    int jg = tid >> 5;                   // 0..7 output group
    float acc[5] = {0.f, 0.f, 0.f, 0.f, 0.f};

    for (int k0 = 0; k0 < DIN; k0 += 32) {
        // load x tile [32 tokens][32 k], coalesced
#pragma unroll
        for (int i = 0; i < 4; i++) {
            int row = (tid >> 5) + i * 8;
            int col = tid & 31;
            xs[row][col] = X[(size_t)(t0 + row) * DIN + k0 + col];
        }
        // load weight tile [32 k][40 cols]
        for (int idx = tid; idx < 32 * NROUTE; idx += 256) {
            int kk = idx / NROUTE, j = idx % NROUTE;
            float v;
            if (j < 8) v = phi[(k0 + kk) * 8 + j];
            else { int kr = j - 8; v = A[(kr >> 2) * (DIN * 4) + (k0 + kk) * 4 + (kr & 3)]; }
            ws[kk][j] = v;
        }
        __syncthreads();
#pragma unroll
        for (int kk = 0; kk < 32; kk++) {
            float xv = xs[tt][kk];
#pragma unroll
            for (int u = 0; u < 5; u++) acc[u] += xv * ws[kk][jg + 8 * u];
        }
        __syncthreads();
    }
#pragma unroll
    for (int u = 0; u < 5; u++) {
        int j = jg + 8 * u;
        int s = s0 + tt;
        if (j < 8) g_mw[(((size_t)b << 10) + s) * 8 + j] = acc[u];
        else       g_Y[((size_t)b * NKR + (j - 8)) * SEQ + s] = acc[u];
    }
}

// ---------------- K3: inclusive cumsum of y over seq, per (b,kr) ----------------
__global__ void scan_kernel() {
    __shared__ float s[SEQ];
    int base = blockIdx.x * SEQ;
    int tid = threadIdx.x;
    s[tid] = g_Y[base + tid];
    for (int off = 1; off < SEQ; off <<= 1) {
        __syncthreads();
        float u = (tid >= off) ? s[tid - off] : 0.f;
        __syncthreads();
        s[tid] += u;
    }
    g_Y[base + tid] = s[tid];
}

// ---------------- K4: base GEMM  out = x @ W^T + bias ----------------
// BM=BN=128, BK=16, 256 threads, 8x8 per thread. Single wave (256 blocks, occ 2).
__global__ void __launch_bounds__(256, 2) gemm_kernel(const float* __restrict__ X,
                                                      const float* __restrict__ W,
                                                      const float* __restrict__ bias,
                                                      float* __restrict__ out) {
    __shared__ float As[16][128];
    __shared__ float Bs[16][128];
    int m0 = blockIdx.y * 128, n0 = blockIdx.x * 128;
    int tid = threadIdx.x;
    int tm = tid >> 4, tn = tid & 15;
    int ldr = tid >> 2;
    int ldc = (tid & 3) * 4;
    const float* Ag = X + (size_t)m0 * DIN;
    const float* Bg = W + (size_t)n0 * DIN;
    float acc[8][8];
#pragma unroll
    for (int i = 0; i < 8; i++)
#pragma unroll
        for (int j = 0; j < 8; j++) acc[i][j] = 0.f;

    for (int k0 = 0; k0 < DIN; k0 += 16) {
#pragma unroll
        for (int h = 0; h < 2; h++) {
            int r = ldr + h * 64;
            float4 v = *(const float4*)&Ag[(size_t)r * DIN + k0 + ldc];
            As[ldc + 0][r] = v.x; As[ldc + 1][r] = v.y; As[ldc + 2][r] = v.z; As[ldc + 3][r] = v.w;
            float4 w = *(const float4*)&Bg[(size_t)r * DIN + k0 + ldc];
            Bs[ldc + 0][r] = w.x; Bs[ldc + 1][r] = w.y; Bs[ldc + 2][r] = w.z; Bs[ldc + 3][r] = w.w;
        }
        __syncthreads();
#pragma unroll
        for (int k = 0; k < 16; k++) {
            float4 a0 = *(const float4*)&As[k][tm * 8];
            float4 a1 = *(const float4*)&As[k][tm * 8 + 4];
            float4 b0 = *(const float4*)&Bs[k][tn * 8];
            float4 b1 = *(const float4*)&Bs[k][tn * 8 + 4];
            float av[8] = {a0.x, a0.y, a0.z, a0.w, a1.x, a1.y, a1.z, a1.w};
            float bv[8] = {b0.x, b0.y, b0.z, b0.w, b1.x, b1.y, b1.z, b1.w};
#pragma unroll
            for (int i = 0; i < 8; i++)
#pragma unroll
                for (int j = 0; j < 8; j++) acc[i][j] += av[i] * bv[j];
        }
        __syncthreads();
    }
    float4 bias0 = *(const float4*)&bias[n0 + tn * 8];
    float4 bias1 = *(const float4*)&bias[n0 + tn * 8 + 4];
#pragma unroll
    for (int i = 0; i < 8; i++) {
        int m = m0 + tm * 8 + i;
        float4 o0 = make_float4(acc[i][0] + bias0.x, acc[i][1] + bias0.y,
                                acc[i][2] + bias0.z, acc[i][3] + bias0.w);
        float4 o1 = make_float4(acc[i][4] + bias1.x, acc[i][5] + bias1.y,
                                acc[i][6] + bias1.z, acc[i][7] + bias1.w);
        *(float4*)&out[(size_t)m * DOUT + n0 + tn * 8] = o0;
        *(float4*)&out[(size_t)m * DOUT + n0 + tn * 8 + 4] = o1;
    }
}

// ---------------- K5: adapter  out += (C .* ar_r) @ B_flat ----------------
// 128 blocks of 32 tokens, 256 threads.
__global__ void __launch_bounds__(256) adapter_kernel(const float* __restrict__ Bflat,
                                                      const int* __restrict__ pad,
                                                      float* __restrict__ out) {
    __shared__ float wr[32][32];   // [token][kr]
    int tileIdx = blockIdx.x;
    int b = tileIdx >> 5;
    int s0 = (tileIdx & 31) << 5;
    int tid = threadIdx.x;
    int thresh = g_meta[b], pstart = g_meta[4 + b];

    if (tid < 32) {
        int t = tid, s = s0 + t;
        if (pad[(b << 10) + s] == 0) {
            for (int kr = 0; kr < 32; kr++) wr[t][kr] = 0.f;
        } else {
            float mwv[8];
            float mx = -1e30f;
#pragma unroll
            for (int j = 0; j < 8; j++) {
                mwv[j] = g_mw[((((size_t)b << 10) + s) << 3) + j];
                mx = fmaxf(mx, mwv[j]);
            }
            float se = 0.f;
#pragma unroll
            for (int j = 0; j < 8; j++) { mwv[j] = expf(mwv[j] - mx); se += mwv[j]; }
            float inv_se = 1.f / se;
            int m = max(thresh, s + 1);
            int cnt = m - pstart;
            if (cnt < 1) cnt = 1;
            float invc = 1.f / (float)cnt;
            for (int kr = 0; kr < 32; kr++) {
                const float* yp = g_Y + ((size_t)b * NKR + kr) * SEQ;
                float wsum = yp[m - 1] - (pstart > 0 ? yp[pstart - 1] : 0.f);
                wr[t][kr] = mwv[kr >> 2] * inv_se * wsum * invc;
            }
        }
    }
    __syncthreads();

    for (int oc = tid; oc < DOUT; oc += 256) {
        float acc[32];
#pragma unroll
        for (int t = 0; t < 32; t++) acc[t] = 0.f;
        for (int kr = 0; kr < 32; kr++) {
            float bv = Bflat[(kr << 10) + oc];
#pragma unroll
            for (int t = 0; t < 32; t++) acc[t] += wr[t][kr] * bv;
        }
#pragma unroll
        for (int t = 0; t < 32; t++) {
            out[((size_t)((b << 10) + s0 + t)) * DOUT + oc] += acc[t];
        }
    }
}

// ---------------- launch ----------------
extern "C" void kernel_launch(void* const* d_in, const int* in_sizes, int n_in,
                              void* d_out, int out_size) {
    const float* x    = (const float*)d_in[0];   // [4,1024,1024]
    const float* phi  = (const float*)d_in[1];   // [1024,8]
    const float* la   = (const float*)d_in[2];   // [8,1024,4]
    const float* lb   = (const float*)d_in[3];   // [8,4,1024]
    const float* W    = (const float*)d_in[4];   // [1024,1024]
    const float* bias = (const float*)d_in[5];   // [1024]
    const int*   inst = (const int*)d_in[6];     // [4,1024]
    const int*   pad  = (const int*)d_in[7];     // [4,1024]
    float* out = (float*)d_out;

    mask_kernel<<<BS, 256>>>(inst, pad);
    router_kernel<<<(BS * SEQ) / 32, 256>>>(x, phi, la);
    scan_kernel<<<BS * NKR, SEQ>>>();
    gemm_kernel<<<dim3(DOUT / 128, (BS * SEQ) / 128), 256>>>(x, W, bias, out);
    adapter_kernel<<<(BS * SEQ) / 32, 256>>>(lb, pad, out);
}

// round 3
// speedup vs baseline: 2.8900x; 2.8900x over previous
#include <cuda_runtime.h>
#include <cstdint>

#define BS 4
#define SEQ 1024
#define DIN 1024
#define DOUT 1024
#define NKR 32

// ---------------- scratch ----------------
__device__ __align__(128) float g_Y[BS * NKR * SEQ];    // y = x@A -> cumsum over s  [b][kr][s]
__device__ __align__(128) float g_mw[BS * SEQ * 8];     // router logits
__device__ __align__(128) float g_WR[BS * SEQ * NKR];   // adapter K-extension (A side) [token][32]
__device__ __align__(128) float g_BE[DOUT * NKR];       // B_flat transposed [n][kr]
__device__ __align__(128) float g_PHIA[40 * DIN];       // [phi|A] transposed, k-contiguous [40][1024]
__device__ int g_meta[8];

// ---------------- helpers ----------------
__device__ __forceinline__ uint32_t smem_u32(const void* p) {
    uint32_t a;
    asm("{ .reg .u64 t; cvta.to.shared.u64 t, %1; cvt.u32.u64 %0, t; }" : "=r"(a) : "l"(p));
    return a;
}
#define CP16(dst, src)  asm volatile("cp.async.cg.shared.global [%0], [%1], 16;" :: "r"(dst), "l"(src))
#define CP_COMMIT()     asm volatile("cp.async.commit_group;" ::: "memory")
#define CP_WAIT0()      asm volatile("cp.async.wait_group 0;" ::: "memory")

__device__ __forceinline__ uint32_t f2tf32(float f) {
    uint32_t u;
    asm("cvt.rna.tf32.f32 %0, %1;" : "=r"(u) : "f"(f));
    return u;
}
__device__ __forceinline__ void mma_tf32(float c[4], const uint32_t a[4], const uint32_t b[2]) {
    asm volatile(
        "mma.sync.aligned.m16n8k8.row.col.f32.tf32.tf32.f32 "
        "{%0,%1,%2,%3}, {%4,%5,%6,%7}, {%8,%9}, {%0,%1,%2,%3};"
        : "+f"(c[0]), "+f"(c[1]), "+f"(c[2]), "+f"(c[3])
        : "r"(a[0]), "r"(a[1]), "r"(a[2]), "r"(a[3]), "r"(b[0]), "r"(b[1]));
}

// ---------------- K0: transposes (phi|A -> k-contig, lb -> [n][kr]) ----------------
__global__ void __launch_bounds__(256) setup_kernel(const float* __restrict__ phi,
                                                    const float* __restrict__ la,
                                                    const float* __restrict__ lb) {
    int idx = blockIdx.x * 256 + threadIdx.x;
    int stride = gridDim.x * 256;
    for (; idx < 40 * DIN + DOUT * NKR; idx += stride) {
        if (idx < 40 * DIN) {
            int n = idx >> 10, k = idx & 1023;
            float v;
            if (n < 8) v = phi[k * 8 + n];
            else { int kr = n - 8; v = la[(kr >> 2) * (DIN * 4) + k * 4 + (kr & 3)]; }
            g_PHIA[idx] = v;
        } else {
            int i2 = idx - 40 * DIN;
            int n = i2 >> 5, kr = i2 & 31;
            g_BE[i2] = lb[kr * DOUT + n];
        }
    }
}

// ---------------- K1: mask params ----------------
__global__ void mask_kernel(const int* __restrict__ inst, const int* __restrict__ pad) {
    int b = blockIdx.x;
    const int* ib = inst + b * SEQ;
    const int* pb = pad + b * SEQ;
    __shared__ int s_sum, s_fi, s_fp;
    if (threadIdx.x == 0) { s_sum = 0; s_fi = 1 << 30; s_fp = 1 << 30; }
    __syncthreads();
    int lsum = 0, lfi = 1 << 30, lfp = 1 << 30;
    for (int i = threadIdx.x; i < SEQ; i += blockDim.x) {
        int iv = ib[i];
        lsum += iv;
        if (iv && i < lfi) lfi = i;
        if (pb[i] && i < lfp) lfp = i;
    }
    atomicAdd(&s_sum, lsum);
    atomicMin(&s_fi, lfi);
    atomicMin(&s_fp, lfp);
    __syncthreads();
    if (threadIdx.x == 0) {
        int fi = (s_fi == (1 << 30)) ? 0 : s_fi;
        int fp = (s_fp == (1 << 30)) ? 0 : s_fp;
        g_meta[b] = fi + s_sum;
        g_meta[4 + b] = fp;
    }
}

// ---------------- K2: router GEMM via mma.sync  [mw|y] = X @ [phi|A] ----------------
// M=4096 (BM=64, 64 blocks), N=40, K=1024, BK=32. 128 threads = 4 warps, 1 m-atom x 5 n-atoms each.
__global__ void __launch_bounds__(128) router_mma(const float* __restrict__ X) {
    __shared__ float As[64][36];
    __shared__ float Bs[40][36];
    int tid = threadIdx.x, wid = tid >> 5, lane = tid & 31;
    int m0 = blockIdx.x * 64;
    float acc[5][4];
#pragma unroll
    for (int n = 0; n < 5; n++)
#pragma unroll
        for (int j = 0; j < 4; j++) acc[n][j] = 0.f;

    for (int i = 0; i < 32; i++) {
        int k0 = i * 32;
#pragma unroll
        for (int c = tid; c < 512; c += 128) {
            int r = c >> 3, cc = c & 7;
            CP16(smem_u32(&As[r][cc * 4]), X + (size_t)(m0 + r) * DIN + k0 + cc * 4);
        }
        for (int c = tid; c < 320; c += 128) {
            int r = c >> 3, cc = c & 7;
            CP16(smem_u32(&Bs[r][cc * 4]), g_PHIA + (size_t)r * DIN + k0 + cc * 4);
        }
        CP_COMMIT();
        CP_WAIT0();
        __syncthreads();
#pragma unroll
        for (int ka = 0; ka < 4; ka++) {
            int kb = ka * 8;
            int row = wid * 16 + (lane >> 2);
            int kk = kb + (lane & 3);
            uint32_t a[4];
            a[0] = f2tf32(As[row][kk]);
            a[1] = f2tf32(As[row + 8][kk]);
            a[2] = f2tf32(As[row][kk + 4]);
            a[3] = f2tf32(As[row + 8][kk + 4]);
#pragma unroll
            for (int n = 0; n < 5; n++) {
                int nr = n * 8 + (lane >> 2);
                uint32_t b[2];
                b[0] = f2tf32(Bs[nr][kb + (lane & 3)]);
                b[1] = f2tf32(Bs[nr][kb + (lane & 3) + 4]);
                mma_tf32(acc[n], a, b);
            }
        }
        __syncthreads();
    }
    // scatter D
    int row = m0 + wid * 16 + (lane >> 2);
#pragma unroll
    for (int n = 0; n < 5; n++) {
#pragma unroll
        for (int j = 0; j < 4; j++) {
            int m = row + ((j >> 1) << 3);
            int col = n * 8 + (lane & 3) * 2 + (j & 1);
            int b = m >> 10, s = m & 1023;
            if (col < 8) g_mw[(((size_t)b << 10) + s) * 8 + col] = acc[n][j];
            else g_Y[((size_t)b * NKR + (col - 8)) * SEQ + s] = acc[n][j];
        }
    }
}

// ---------------- K3: inclusive cumsum ----------------
__global__ void scan_kernel() {
    __shared__ float s[SEQ];
    int base = blockIdx.x * SEQ;
    int tid = threadIdx.x;
    s[tid] = g_Y[base + tid];
    for (int off = 1; off < SEQ; off <<= 1) {
        __syncthreads();
        float u = (tid >= off) ? s[tid - off] : 0.f;
        __syncthreads();
        s[tid] += u;
    }
    g_Y[base + tid] = s[tid];
}

// ---------------- K4: wr weights ----------------
__global__ void __launch_bounds__(128) wr_prep(const int* __restrict__ pad) {
    int token = blockIdx.x * 128 + threadIdx.x;
    int b = token >> 10, s = token & 1023;
    float* wr = g_WR + (size_t)token * NKR;
    if (pad[(b << 10) + s] == 0) {
#pragma unroll
        for (int kr = 0; kr < NKR; kr++) wr[kr] = 0.f;
        return;
    }
    int thresh = g_meta[b], pstart = g_meta[4 + b];
    float mwv[8];
    float mx = -1e30f;
#pragma unroll
    for (int j = 0; j < 8; j++) {
        mwv[j] = g_mw[((((size_t)b << 10) + s) << 3) + j];
        mx = fmaxf(mx, mwv[j]);
    }
    float se = 0.f;
#pragma unroll
    for (int j = 0; j < 8; j++) { mwv[j] = expf(mwv[j] - mx); se += mwv[j]; }
    float inv_se = 1.f / se;
    int m = max(thresh, s + 1);
    int cnt = m - pstart;
    if (cnt < 1) cnt = 1;
    float invc = 1.f / (float)cnt;
#pragma unroll
    for (int kr = 0; kr < NKR; kr++) {
        const float* yp = g_Y + ((size_t)b * NKR + kr) * SEQ;
        float wsum = yp[m - 1] - (pstart > 0 ? yp[pstart - 1] : 0.f);
        wr[kr] = mwv[kr >> 2] * inv_se * wsum * invc;
    }
}

// ---------------- K5: fused GEMM  out = [X|wr] @ [[W^T];[Bflat]] + bias ----------------
// BM=BN=128, BK=32, K=1056 (33 tiles). 256 threads = 8 warps (2m x 4n), warp tile 64x32.
__global__ void __launch_bounds__(256, 2) gemm_mma(const float* __restrict__ X,
                                                   const float* __restrict__ W,
                                                   const float* __restrict__ bias,
                                                   float* __restrict__ out) {
    __shared__ float As[128][36];
    __shared__ float Bs[128][36];
    int tid = threadIdx.x, wid = tid >> 5, lane = tid & 31;
    int wm = wid >> 2, wn = wid & 3;                  // 2 x 4 warps
    int m0 = blockIdx.y * 128, n0 = blockIdx.x * 128;

    float acc[4][4][4];
#pragma unroll
    for (int i = 0; i < 4; i++)
#pragma unroll
        for (int j = 0; j < 4; j++)
#pragma unroll
            for (int k = 0; k < 4; k++) acc[i][j][k] = 0.f;

    for (int i = 0; i < 33; i++) {
        int k0 = i * 32;
        bool ext = (i == 32);
#pragma unroll
        for (int c = tid; c < 1024; c += 256) {
            int r = c >> 3, cc = c & 7;
            const float* srcA = ext ? g_WR + (size_t)(m0 + r) * NKR + cc * 4
                                    : X + (size_t)(m0 + r) * DIN + k0 + cc * 4;
            CP16(smem_u32(&As[r][cc * 4]), srcA);
            const float* srcB = ext ? g_BE + (size_t)(n0 + r) * NKR + cc * 4
                                    : W + (size_t)(n0 + r) * DIN + k0 + cc * 4;
            CP16(smem_u32(&Bs[r][cc * 4]), srcB);
        }
        CP_COMMIT();
        CP_WAIT0();
        __syncthreads();
#pragma unroll
        for (int ka = 0; ka < 4; ka++) {
            int kb = ka * 8;
            int kk = kb + (lane & 3);
            uint32_t a[4][4];
#pragma unroll
            for (int mi = 0; mi < 4; mi++) {
                int row = wm * 64 + mi * 16 + (lane >> 2);
                a[mi][0] = f2tf32(As[row][kk]);
                a[mi][1] = f2tf32(As[row + 8][kk]);
                a[mi][2] = f2tf32(As[row][kk + 4]);
                a[mi][3] = f2tf32(As[row + 8][kk + 4]);
            }
#pragma unroll
            for (int ni = 0; ni < 4; ni++) {
                int nr = wn * 32 + ni * 8 + (lane >> 2);
                uint32_t b[2];
                b[0] = f2tf32(Bs[nr][kk]);
                b[1] = f2tf32(Bs[nr][kk + 4]);
#pragma unroll
                for (int mi = 0; mi < 4; mi++) mma_tf32(acc[mi][ni], a[mi], b);
            }
        }
        __syncthreads();
    }

    // epilogue: bias + store
#pragma unroll
    for (int ni = 0; ni < 4; ni++) {
        int col = n0 + wn * 32 + ni * 8 + (lane & 3) * 2;
        float b0 = bias[col], b1 = bias[col + 1];
#pragma unroll
        for (int mi = 0; mi < 4; mi++) {
            int row = m0 + wm * 64 + mi * 16 + (lane >> 2);
            float2 v0 = make_float2(acc[mi][ni][0] + b0, acc[mi][ni][1] + b1);
            float2 v1 = make_float2(acc[mi][ni][2] + b0, acc[mi][ni][3] + b1);
            *(float2*)&out[(size_t)row * DOUT + col] = v0;
            *(float2*)&out[(size_t)(row + 8) * DOUT + col] = v1;
        }
    }
}

// ---------------- launch ----------------
extern "C" void kernel_launch(void* const* d_in, const int* in_sizes, int n_in,
                              void* d_out, int out_size) {
    const float* x    = (const float*)d_in[0];
    const float* phi  = (const float*)d_in[1];
    const float* la   = (const float*)d_in[2];
    const float* lb   = (const float*)d_in[3];
    const float* W    = (const float*)d_in[4];
    const float* bias = (const float*)d_in[5];
    const int*   inst = (const int*)d_in[6];
    const int*   pad  = (const int*)d_in[7];
    float* out = (float*)d_out;

    setup_kernel<<<64, 256>>>(phi, la, lb);
    mask_kernel<<<BS, 256>>>(inst, pad);
    router_mma<<<(BS * SEQ) / 64, 128>>>(x);
    scan_kernel<<<BS * NKR, SEQ>>>();
    wr_prep<<<(BS * SEQ) / 128, 128>>>(pad);
    gemm_mma<<<dim3(DOUT / 128, (BS * SEQ) / 128), 256>>>(x, W, bias, out);
}